// round 4
// baseline (speedup 1.0000x reference)
#include <cuda_runtime.h>
#include <math.h>

#define N_   4
#define H_   64
#define W_   64
#define C_   256
#define CM_  64
#define E_   100     // enc output channels = 25*4
#define HW_  4096    // H*W
#define Q_   65536   // N * 128 * 128 (output pixels)

typedef unsigned long long u64;

// ---- scratch (device globals; allocation-free contract) ----
__device__ float g_down[N_ * CM_ * HW_];        // 4 MB   (N,64,64,64)
__device__ float g_kern[N_ * HW_ * E_];         // 6.5 MB (N,H,W,25,4) flattened
__device__ float g_R[C_ * Q_];                  // 64 MB  [c][q], q = n*16384 + ho*128 + wo

// ---- f32x2 packed fp32 helpers (FFMA2 path, exact fp32) ----
__device__ __forceinline__ u64 pk2(float a, float b) {
    u64 r;
    asm("mov.b64 %0, {%1, %2};" : "=l"(r)
        : "r"(__float_as_uint(a)), "r"(__float_as_uint(b)));
    return r;
}
__device__ __forceinline__ void fma2(u64& d, u64 a, u64 b) {
    asm("fma.rn.f32x2 %0, %1, %2, %0;" : "+l"(d) : "l"(a), "l"(b));
}
__device__ __forceinline__ float2 up2(u64 v) {
    unsigned int lo, hi;
    asm("mov.b64 {%0, %1}, %2;" : "=r"(lo), "=r"(hi) : "l"(v));
    return make_float2(__uint_as_float(lo), __uint_as_float(hi));
}

// ============================================================
// Kernel 1: 1x1 down conv  (N,256,H,W) -> (N,64,H,W)   [f32x2]
// block = (n, row): 64 pixels x 64 out channels, 256 threads
// ============================================================
__global__ __launch_bounds__(256) void k_down(const float* __restrict__ x,
                                              const float* __restrict__ w,
                                              const float* __restrict__ b) {
    __shared__ u64 Ws[64 * 33];                 // [c][k] dup pairs, pitch 33 (16.9 KB)
    __shared__ __align__(16) float Xs[32][64];  // [k][p] (8 KB)
    int n = blockIdx.x >> 6, row = blockIdx.x & 63;
    const float* xb = x + ((size_t)n * C_) * HW_ + row * 64;
    int t = threadIdx.x;
    int pg = t & 15, cg = t >> 4;
    u64 acc[4][2] = {};

    for (int k0 = 0; k0 < 256; k0 += 32) {
        for (int i = t; i < 2048; i += 256) {
            int c = i >> 5, k = i & 31;
            float wv = w[c * 256 + k0 + k];      // coalesced in k
            Ws[c * 33 + k] = pk2(wv, wv);        // consecutive u64 store: conflict-free
        }
        for (int i = t; i < 2048; i += 256) {
            int a = i >> 6, bb = i & 63;
            Xs[a][bb] = xb[(size_t)(k0 + a) * HW_ + bb];
        }
        __syncthreads();
        #pragma unroll 8
        for (int k = 0; k < 32; ++k) {
            float4 xv = *(const float4*)&Xs[k][pg * 4];
            u64 x0 = pk2(xv.x, xv.y), x1 = pk2(xv.z, xv.w);
            #pragma unroll
            for (int cc = 0; cc < 4; ++cc) {
                u64 wv = Ws[(cg * 4 + cc) * 33 + k];   // broadcast LDS.64
                fma2(acc[cc][0], wv, x0);
                fma2(acc[cc][1], wv, x1);
            }
        }
        __syncthreads();
    }
    #pragma unroll
    for (int cc = 0; cc < 4; ++cc) {
        int c = cg * 4 + cc;
        float bias = b[c];
        float2 lo = up2(acc[cc][0]), hi = up2(acc[cc][1]);
        float4 v = make_float4(lo.x + bias, lo.y + bias, hi.x + bias, hi.y + bias);
        *(float4*)&g_down[((size_t)(n * CM_ + c)) * HW_ + row * 64 + pg * 4] = v;
    }
}

// ============================================================
// Kernel 2: 3x3 enc conv (64->100) + fused softmax over 25  [f32x2 kidx-pairs]
// block = (n, row); thread = (pixel p, d-subgroup dg); softmax thread-local
// ============================================================
__global__ __launch_bounds__(256) void k_enc(const float* __restrict__ we,
                                             const float* __restrict__ be) {
    __shared__ __align__(16) u64   Wp[4][12][8][10];  // paired kidx weights, 30720 B
    __shared__ __align__(16) float W24[4][8][12];     // kidx=24 weights, 1536 B
    __shared__ float Xs[8][3][68];                    // [ci][row][w+halo], 6528 B
    int n = blockIdx.x >> 6, h = blockIdx.x & 63;
    int t = threadIdx.x;
    int p = t & 63, dg = t >> 6;
    u64   accp[12] = {};
    float acc24 = 0.f;

    for (int c0 = 0; c0 < CM_; c0 += 8) {
        // weights for this channel chunk: pack (kidx 2kp, 2kp+1) into u64
        for (int i = t; i < 3456; i += 256) {
            int dgi = i / 864, rem = i % 864;
            int kp = rem / 72, rem2 = rem % 72;
            int ci = rem2 / 9, r = rem2 % 9;
            int base = (c0 + ci) * 9 + r;
            float wa = we[(2 * kp * 4 + dgi) * (CM_ * 9) + base];
            float wb = we[((2 * kp + 1) * 4 + dgi) * (CM_ * 9) + base];
            Wp[dgi][kp][ci][r] = pk2(wa, wb);
        }
        for (int i = t; i < 288; i += 256) {
            int dgi = i / 72, rem = i % 72, ci = rem / 9, r = rem % 9;
            W24[dgi][ci][r] = we[(96 + dgi) * (CM_ * 9) + (c0 + ci) * 9 + r];
        }
        for (int i = t; i < 8 * 3 * 66; i += 256) {
            int c = i / 198, rem = i % 198, r = rem / 66, wq = rem % 66;
            int hh = h - 1 + r, ww = wq - 1;
            float v = 0.f;
            if (hh >= 0 && hh < 64 && ww >= 0 && ww < 64)
                v = g_down[((size_t)(n * CM_ + c0 + c) * 64 + hh) * 64 + ww];
            Xs[c][r][wq] = v;
        }
        __syncthreads();

        for (int ci = 0; ci < 8; ++ci) {
            float xr[9];
            u64 xd[9];
            #pragma unroll
            for (int kh = 0; kh < 3; ++kh)
                #pragma unroll
                for (int kw = 0; kw < 3; ++kw)
                    xr[kh * 3 + kw] = Xs[ci][kh][p + kw];
            #pragma unroll
            for (int j = 0; j < 9; ++j) xd[j] = pk2(xr[j], xr[j]);

            #pragma unroll
            for (int kp = 0; kp < 12; ++kp) {
                const u64* wr = &Wp[dg][kp][ci][0];
                ulonglong2 wA = *(const ulonglong2*)wr;
                ulonglong2 wB = *(const ulonglong2*)(wr + 2);
                ulonglong2 wC = *(const ulonglong2*)(wr + 4);
                ulonglong2 wD = *(const ulonglong2*)(wr + 6);
                u64 w8 = wr[8];
                fma2(accp[kp], wA.x, xd[0]); fma2(accp[kp], wA.y, xd[1]);
                fma2(accp[kp], wB.x, xd[2]); fma2(accp[kp], wB.y, xd[3]);
                fma2(accp[kp], wC.x, xd[4]); fma2(accp[kp], wC.y, xd[5]);
                fma2(accp[kp], wD.x, xd[6]); fma2(accp[kp], wD.y, xd[7]);
                fma2(accp[kp], w8, xd[8]);
            }
            const float* w24r = &W24[dg][ci][0];
            float4 wa = *(const float4*)w24r;
            float4 wb = *(const float4*)(w24r + 4);
            float w8s = w24r[8];
            acc24 += wa.x * xr[0] + wa.y * xr[1] + wa.z * xr[2] + wa.w * xr[3]
                   + wb.x * xr[4] + wb.y * xr[5] + wb.z * xr[6] + wb.w * xr[7]
                   + w8s * xr[8];
        }
        __syncthreads();
    }

    // unpack + per-thread softmax over the 25 kidx
    float a[25];
    #pragma unroll
    for (int kp = 0; kp < 12; ++kp) {
        float2 f = up2(accp[kp]);
        a[2 * kp] = f.x; a[2 * kp + 1] = f.y;
    }
    a[24] = acc24;
    float m = -1e30f;
    #pragma unroll
    for (int k = 0; k < 25; ++k) { a[k] += be[k * 4 + dg]; m = fmaxf(m, a[k]); }
    float s = 0.f;
    #pragma unroll
    for (int k = 0; k < 25; ++k) { a[k] = expf(a[k] - m); s += a[k]; }
    float inv = 1.f / s;
    float* kp_ = &g_kern[((size_t)(n * HW_ + h * 64 + p)) * E_];
    #pragma unroll
    for (int k = 0; k < 25; ++k) kp_[k * 4 + dg] = a[k] * inv;
}

// ============================================================
// Kernel 3: CARAFE reassembly -> g_R[c][q] (pixel-shuffled)  [f32x2]
// block = (n, row); thread = (pixel p, channel subgroup g)
// ============================================================
__global__ __launch_bounds__(256) void k_reasm(const float* __restrict__ x) {
    __shared__ __align__(16) float Ks[64 * 100];  // pitch 100: (400p/16)%8=p%8 -> f4 conflict-free
    __shared__ float Xs[16 * 5 * 68];             // 21760 B
    int n = blockIdx.x >> 6, h = blockIdx.x & 63;
    int t = threadIdx.x;
    int p = t & 63, g = t >> 6;

    {   // g_kern row is 6400 contiguous floats -> straight f4 copy
        const float4* src = (const float4*)&g_kern[((size_t)(n * HW_ + h * 64)) * E_];
        float4* dst = (float4*)Ks;
        for (int i = t; i < 1600; i += 256) dst[i] = src[i];
    }

    for (int c0 = 0; c0 < C_; c0 += 16) {
        __syncthreads();
        for (int i = t; i < 16 * 5 * 68; i += 256) {
            int c = i / 340, rem = i % 340, r = rem / 68, wq = rem % 68;
            int hh = h - 2 + r, ww = wq - 2;
            float v = 0.f;
            if (hh >= 0 && hh < 64 && ww >= 0 && ww < 64)
                v = x[((size_t)(n * C_ + c0 + c) * 64 + hh) * 64 + ww];
            Xs[i] = v;
        }
        __syncthreads();

        u64 acc[4][2] = {};
        const float* kr = &Ks[p * 100];
        #pragma unroll
        for (int kidx = 0; kidx < 25; ++kidx) {
            int ih = kidx / 5, iw = kidx % 5;
            ulonglong2 kk = *(const ulonglong2*)&kr[kidx * 4];  // (k0,k1),(k2,k3)
            #pragma unroll
            for (int cc = 0; cc < 4; ++cc) {
                float xv = Xs[(g * 4 + cc) * 340 + ih * 68 + p + iw];
                u64 xd = pk2(xv, xv);
                fma2(acc[cc][0], kk.x, xd);
                fma2(acc[cc][1], kk.y, xd);
            }
        }
        #pragma unroll
        for (int cc = 0; cc < 4; ++cc) {
            int c = c0 + g * 4 + cc;
            float* rp = &g_R[(size_t)c * Q_ + n * 16384 + (2 * h) * 128 + 2 * p];
            float2 lo = up2(acc[cc][0]), hi = up2(acc[cc][1]);
            *(float2*)rp         = lo;   // d=0,1 -> row 2h
            *(float2*)(rp + 128) = hi;   // d=2,3 -> row 2h+1
        }
    }
}

// ============================================================
// Kernel 4: 1x1 out conv = GEMM 256x256 @ 65536  [f32x2, 8x8 tile]
// BM=64 oc, BN=256 q, BK=32; output written directly in d_out layout
// ============================================================
__global__ __launch_bounds__(256) void k_out(const float* __restrict__ w,
                                             const float* __restrict__ b,
                                             float* __restrict__ out) {
    __shared__ __align__(16) float Xs[32][256];   // 32 KB
    __shared__ __align__(16) u64 Wd[32 * 64];     // [k][oc] dup pairs, XOR swizzled, 16 KB
    int t = threadIdx.x;
    int qbase = blockIdx.x * 256;
    int ocbase = blockIdx.y * 64;
    int tq = t & 31, tc = t >> 5;
    int q0 = tq * 4, oc0 = tc * 8;
    u64 acc[8][4] = {};

    for (int k0 = 0; k0 < 256; k0 += 32) {
        for (int i = t; i < 2048; i += 256) {
            int k = i & 31, oc = i >> 5;                 // coalesced gld over k
            float wv = w[(ocbase + oc) * 256 + k0 + k];
            Wd[k * 64 + ((oc + 2 * k) & 63)] = pk2(wv, wv);  // swizzle: near conflict-free fill
        }
        for (int i = t * 4; i < 8192; i += 1024) {
            int k = i >> 8, q = i & 255;
            *(float4*)&Xs[k][q] =
                *(const float4*)&g_R[(size_t)(k0 + k) * Q_ + qbase + q];
        }
        __syncthreads();
        #pragma unroll 8
        for (int k = 0; k < 32; ++k) {
            float4 xA = *(const float4*)&Xs[k][q0];
            float4 xB = *(const float4*)&Xs[k][q0 + 128];
            u64 a0 = pk2(xA.x, xA.y), a1 = pk2(xA.z, xA.w);
            u64 b0 = pk2(xB.x, xB.y), b1 = pk2(xB.z, xB.w);
            const u64* wrow = &Wd[k * 64];
            int sw = 2 * k;
            #pragma unroll
            for (int i = 0; i < 4; ++i) {
                // 16B-aligned broadcast: (oc0+2i+sw)&63 is even, no wrap within the pair
                ulonglong2 ww = *(const ulonglong2*)&wrow[(oc0 + 2 * i + sw) & 63];
                fma2(acc[2 * i][0], ww.x, a0); fma2(acc[2 * i][1], ww.x, a1);
                fma2(acc[2 * i][2], ww.x, b0); fma2(acc[2 * i][3], ww.x, b1);
                fma2(acc[2 * i + 1][0], ww.y, a0); fma2(acc[2 * i + 1][1], ww.y, a1);
                fma2(acc[2 * i + 1][2], ww.y, b0); fma2(acc[2 * i + 1][3], ww.y, b1);
            }
        }
        __syncthreads();
    }

    int q = qbase + q0;
    int n = q >> 14, pos = q & 16383;    // q0+128 stays in same image (qbase % 256 == 0)
    #pragma unroll
    for (int i = 0; i < 8; ++i) {
        int oc = ocbase + oc0 + i;
        float bias = b[oc];
        float* op = &out[((size_t)n * 256 + oc) * 16384 + pos];
        float2 p0 = up2(acc[i][0]), p1 = up2(acc[i][1]);
        float2 p2 = up2(acc[i][2]), p3 = up2(acc[i][3]);
        *(float4*)op =
            make_float4(p0.x + bias, p0.y + bias, p1.x + bias, p1.y + bias);
        *(float4*)(op + 128) =
            make_float4(p2.x + bias, p2.y + bias, p3.x + bias, p3.y + bias);
    }
}

// ============================================================
extern "C" void kernel_launch(void* const* d_in, const int* in_sizes, int n_in,
                              void* d_out, int out_size) {
    const float* x      = (const float*)d_in[0];
    const float* w_down = (const float*)d_in[1];
    const float* b_down = (const float*)d_in[2];
    const float* w_enc  = (const float*)d_in[3];
    const float* b_enc  = (const float*)d_in[4];
    const float* w_out  = (const float*)d_in[5];
    const float* b_out  = (const float*)d_in[6];
    float* out = (float*)d_out;

    k_down <<<N_ * H_, 256>>>(x, w_down, b_down);
    k_enc  <<<N_ * H_, 256>>>(w_enc, b_enc);
    k_reasm<<<N_ * H_, 256>>>(x);
    k_out  <<<dim3(Q_ / 256, C_ / 64), 256>>>(w_out, b_out, out);
}

// round 5
// speedup vs baseline: 1.7308x; 1.7308x over previous
#include <cuda_runtime.h>
#include <math.h>

#define N_   4
#define H_   64
#define W_   64
#define C_   256
#define CM_  64
#define E_   100     // enc output channels = 25*4
#define HW_  4096    // H*W
#define QL_  16384   // N * 64 * 64 (low-res pixels)

typedef unsigned long long u64;

// ---- scratch (device globals; allocation-free contract) ----
__device__ float g_down[N_ * CM_ * HW_];        // 4 MB   (N,64,64,64)
__device__ float g_kern[N_ * HW_ * E_];         // 6.5 MB (N,H,W,25,4) flattened
__device__ float g_Y[C_ * QL_];                 // 16 MB  [oc][n*4096 + h*64 + w]

// ---- f32x2 packed fp32 helpers (FFMA2 path, exact fp32) ----
__device__ __forceinline__ u64 pk2(float a, float b) {
    u64 r;
    asm("mov.b64 %0, {%1, %2};" : "=l"(r)
        : "r"(__float_as_uint(a)), "r"(__float_as_uint(b)));
    return r;
}
__device__ __forceinline__ void fma2(u64& d, u64 a, u64 b) {
    asm("fma.rn.f32x2 %0, %1, %2, %0;" : "+l"(d) : "l"(a), "l"(b));
}
__device__ __forceinline__ float2 up2(u64 v) {
    unsigned int lo, hi;
    asm("mov.b64 {%0, %1}, %2;" : "=r"(lo), "=r"(hi) : "l"(v));
    return make_float2(__uint_as_float(lo), __uint_as_float(hi));
}

// ============================================================
// Kernel 1: 1x1 down conv  (N,256,H,W) -> (N,64,H,W)   [f32x2]
// block = (n, row): 64 pixels x 64 out channels, 256 threads
// ============================================================
__global__ __launch_bounds__(256) void k_down(const float* __restrict__ x,
                                              const float* __restrict__ w,
                                              const float* __restrict__ b) {
    __shared__ u64 Ws[64 * 33];                 // [c][k] dup pairs, pitch 33
    __shared__ __align__(16) float Xs[32][64];  // [k][p]
    int n = blockIdx.x >> 6, row = blockIdx.x & 63;
    const float* xb = x + ((size_t)n * C_) * HW_ + row * 64;
    int t = threadIdx.x;
    int pg = t & 15, cg = t >> 4;
    u64 acc[4][2] = {};

    for (int k0 = 0; k0 < 256; k0 += 32) {
        for (int i = t; i < 2048; i += 256) {
            int c = i >> 5, k = i & 31;
            float wv = w[c * 256 + k0 + k];
            Ws[c * 33 + k] = pk2(wv, wv);
        }
        for (int i = t; i < 2048; i += 256) {
            int a = i >> 6, bb = i & 63;
            Xs[a][bb] = xb[(size_t)(k0 + a) * HW_ + bb];
        }
        __syncthreads();
        #pragma unroll 8
        for (int k = 0; k < 32; ++k) {
            float4 xv = *(const float4*)&Xs[k][pg * 4];
            u64 x0 = pk2(xv.x, xv.y), x1 = pk2(xv.z, xv.w);
            #pragma unroll
            for (int cc = 0; cc < 4; ++cc) {
                u64 wv = Ws[(cg * 4 + cc) * 33 + k];
                fma2(acc[cc][0], wv, x0);
                fma2(acc[cc][1], wv, x1);
            }
        }
        __syncthreads();
    }
    #pragma unroll
    for (int cc = 0; cc < 4; ++cc) {
        int c = cg * 4 + cc;
        float bias = b[c];
        float2 lo = up2(acc[cc][0]), hi = up2(acc[cc][1]);
        float4 v = make_float4(lo.x + bias, lo.y + bias, hi.x + bias, hi.y + bias);
        *(float4*)&g_down[((size_t)(n * CM_ + c)) * HW_ + row * 64 + pg * 4] = v;
    }
}

// ============================================================
// Kernel 2: 3x3 enc conv (64->100) + fused softmax over 25  [f32x2 kidx-pairs]
// block = (n, row); thread = (pixel p, d-subgroup dg); softmax thread-local
// ============================================================
__global__ __launch_bounds__(256) void k_enc(const float* __restrict__ we,
                                             const float* __restrict__ be) {
    __shared__ __align__(16) u64   Wp[4][12][8][10];  // paired kidx weights
    __shared__ __align__(16) float W24[4][8][12];     // kidx=24 weights
    __shared__ float Xs[8][3][68];                    // [ci][row][w+halo]
    int n = blockIdx.x >> 6, h = blockIdx.x & 63;
    int t = threadIdx.x;
    int p = t & 63, dg = t >> 6;
    u64   accp[12] = {};
    float acc24 = 0.f;

    for (int c0 = 0; c0 < CM_; c0 += 8) {
        for (int i = t; i < 3456; i += 256) {
            int dgi = i / 864, rem = i % 864;
            int kp = rem / 72, rem2 = rem % 72;
            int ci = rem2 / 9, r = rem2 % 9;
            int base = (c0 + ci) * 9 + r;
            float wa = we[(2 * kp * 4 + dgi) * (CM_ * 9) + base];
            float wb = we[((2 * kp + 1) * 4 + dgi) * (CM_ * 9) + base];
            Wp[dgi][kp][ci][r] = pk2(wa, wb);
        }
        for (int i = t; i < 288; i += 256) {
            int dgi = i / 72, rem = i % 72, ci = rem / 9, r = rem % 9;
            W24[dgi][ci][r] = we[(96 + dgi) * (CM_ * 9) + (c0 + ci) * 9 + r];
        }
        for (int i = t; i < 8 * 3 * 66; i += 256) {
            int c = i / 198, rem = i % 198, r = rem / 66, wq = rem % 66;
            int hh = h - 1 + r, ww = wq - 1;
            float v = 0.f;
            if (hh >= 0 && hh < 64 && ww >= 0 && ww < 64)
                v = g_down[((size_t)(n * CM_ + c0 + c) * 64 + hh) * 64 + ww];
            Xs[c][r][wq] = v;
        }
        __syncthreads();

        for (int ci = 0; ci < 8; ++ci) {
            float xr[9];
            u64 xd[9];
            #pragma unroll
            for (int kh = 0; kh < 3; ++kh)
                #pragma unroll
                for (int kw = 0; kw < 3; ++kw)
                    xr[kh * 3 + kw] = Xs[ci][kh][p + kw];
            #pragma unroll
            for (int j = 0; j < 9; ++j) xd[j] = pk2(xr[j], xr[j]);

            #pragma unroll
            for (int kp = 0; kp < 12; ++kp) {
                const u64* wr = &Wp[dg][kp][ci][0];
                ulonglong2 wA = *(const ulonglong2*)wr;
                ulonglong2 wB = *(const ulonglong2*)(wr + 2);
                ulonglong2 wC = *(const ulonglong2*)(wr + 4);
                ulonglong2 wD = *(const ulonglong2*)(wr + 6);
                u64 w8 = wr[8];
                fma2(accp[kp], wA.x, xd[0]); fma2(accp[kp], wA.y, xd[1]);
                fma2(accp[kp], wB.x, xd[2]); fma2(accp[kp], wB.y, xd[3]);
                fma2(accp[kp], wC.x, xd[4]); fma2(accp[kp], wC.y, xd[5]);
                fma2(accp[kp], wD.x, xd[6]); fma2(accp[kp], wD.y, xd[7]);
                fma2(accp[kp], w8, xd[8]);
            }
            const float* w24r = &W24[dg][ci][0];
            float4 wa = *(const float4*)w24r;
            float4 wb = *(const float4*)(w24r + 4);
            float w8s = w24r[8];
            acc24 += wa.x * xr[0] + wa.y * xr[1] + wa.z * xr[2] + wa.w * xr[3]
                   + wb.x * xr[4] + wb.y * xr[5] + wb.z * xr[6] + wb.w * xr[7]
                   + w8s * xr[8];
        }
        __syncthreads();
    }

    float a[25];
    #pragma unroll
    for (int kp = 0; kp < 12; ++kp) {
        float2 f = up2(accp[kp]);
        a[2 * kp] = f.x; a[2 * kp + 1] = f.y;
    }
    a[24] = acc24;
    float m = -1e30f;
    #pragma unroll
    for (int k = 0; k < 25; ++k) { a[k] += be[k * 4 + dg]; m = fmaxf(m, a[k]); }
    float s = 0.f;
    #pragma unroll
    for (int k = 0; k < 25; ++k) { a[k] = expf(a[k] - m); s += a[k]; }
    float inv = 1.f / s;
    float* kp_ = &g_kern[((size_t)(n * HW_ + h * 64 + p)) * E_];
    #pragma unroll
    for (int k = 0; k < 25; ++k) kp_[k * 4 + dg] = a[k] * inv;
}

// ============================================================
// Kernel 3: 1x1 out conv on LOW-RES input (commuted with reassembly)
// Y[oc][q] = sum_k w_out[oc][k] * x[k][q],  NO bias (padding must stay zero)
// GEMM 256oc x 16384q x 256k; BM=64, BN=128, BK=32  [f32x2, proven R3 tile]
// ============================================================
__global__ __launch_bounds__(256) void k_y(const float* __restrict__ x,
                                           const float* __restrict__ w) {
    __shared__ u64 Wd[64][32];                       // packed (w,w) pairs
    __shared__ __align__(16) float Xs[32][128];
    int t = threadIdx.x;
    int qbase = blockIdx.x * 128;
    int ocbase = blockIdx.y * 64;
    int n = qbase >> 12, pos = qbase & 4095;         // pos % 128 == 0
    const float* xb = x + (size_t)n * (C_ * HW_) + pos;
    int tq = t & 31, tc = t >> 5;
    int q0 = tq * 4, oc0 = tc * 8;
    u64 acc[8][2] = {};

    for (int k0 = 0; k0 < 256; k0 += 32) {
        for (int i = t; i < 2048; i += 256) {
            int c = i >> 5, k = i & 31;              // c const per warp -> coalesced gld
            float wv = w[(ocbase + c) * 256 + k0 + k];
            Wd[c][k] = pk2(wv, wv);
        }
        for (int i = t * 4; i < 4096; i += 1024) {
            int k = i >> 7, q = i & 127;
            *(float4*)&Xs[k][q] = *(const float4*)&xb[(size_t)(k0 + k) * HW_ + q];
        }
        __syncthreads();
        #pragma unroll 8
        for (int k = 0; k < 32; ++k) {
            float4 xv = *(const float4*)&Xs[k][q0];
            u64 xlo = pk2(xv.x, xv.y);
            u64 xhi = pk2(xv.z, xv.w);
            #pragma unroll
            for (int i = 0; i < 8; ++i) {
                u64 w2 = Wd[oc0 + i][k];             // warp-broadcast LDS.64
                fma2(acc[i][0], w2, xlo);
                fma2(acc[i][1], w2, xhi);
            }
        }
        __syncthreads();
    }

    #pragma unroll
    for (int i = 0; i < 8; ++i) {
        int oc = ocbase + oc0 + i;
        float2 lo = up2(acc[i][0]);
        float2 hi = up2(acc[i][1]);
        float4 v = make_float4(lo.x, lo.y, hi.x, hi.y);
        *(float4*)&g_Y[(size_t)oc * QL_ + qbase + q0] = v;
    }
}

// ============================================================
// Kernel 4: fused CARAFE reassembly on Y + pixel shuffle + bias -> d_out
// out[oc, 2h+i, 2w+j] = sum_k kern[k, d=(i,j), h, w] * Yp[oc, h+kh-2, w+kw-2] + b[oc]
// block = (n, row); thread = (pixel p, oc-subgroup g); 32-oc chunks, cc=8/thread
// ============================================================
__global__ __launch_bounds__(256) void k_fuse(const float* __restrict__ bo,
                                              float* __restrict__ out) {
    __shared__ __align__(16) float Ks[64 * 100];  // pitch 100, LDS.128 phase-conflict-free
    __shared__ float Xs[32 * 5 * 68];             // 43.5 KB  (Y chunk + halo)
    int n = blockIdx.x >> 6, h = blockIdx.x & 63;
    int t = threadIdx.x;
    int p = t & 63, g = t >> 6;

    {   // g_kern row = 6400 contiguous floats -> straight f4 copy
        const float4* src = (const float4*)&g_kern[((size_t)(n * HW_ + h * 64)) * E_];
        float4* dst = (float4*)Ks;
        for (int i = t; i < 1600; i += 256) dst[i] = src[i];
    }

    for (int c0 = 0; c0 < C_; c0 += 32) {
        __syncthreads();   // prev compute done (also covers Ks fill on first iter)
        for (int i = t; i < 32 * 5 * 68; i += 256) {
            int c = i / 340, rem = i % 340, r = rem / 68, wq = rem % 68;
            int hh = h - 2 + r, ww = wq - 2;
            float v = 0.f;
            if (hh >= 0 && hh < 64 && ww >= 0 && ww < 64)
                v = g_Y[(size_t)(c0 + c) * QL_ + n * 4096 + hh * 64 + ww];
            Xs[i] = v;
        }
        __syncthreads();

        u64 acc[8][2] = {};
        const float* kr = &Ks[p * 100];
        #pragma unroll
        for (int kidx = 0; kidx < 25; ++kidx) {
            int ih = kidx / 5, iw = kidx % 5;
            ulonglong2 kk = *(const ulonglong2*)&kr[kidx * 4];  // (d0,d1),(d2,d3)
            int base = ih * 68 + p + iw;
            #pragma unroll
            for (int cc = 0; cc < 8; ++cc) {
                float xv = Xs[(g * 8 + cc) * 340 + base];
                u64 xd = pk2(xv, xv);
                fma2(acc[cc][0], kk.x, xd);
                fma2(acc[cc][1], kk.y, xd);
            }
        }
        #pragma unroll
        for (int cc = 0; cc < 8; ++cc) {
            int oc = c0 + g * 8 + cc;
            float bias = bo[oc];
            float2 lo = up2(acc[cc][0]), hi = up2(acc[cc][1]);
            float* op = &out[(((size_t)n * 256 + oc) * 128 + 2 * h) * 128 + 2 * p];
            *(float2*)op         = make_float2(lo.x + bias, lo.y + bias); // d0,d1
            *(float2*)(op + 128) = make_float2(hi.x + bias, hi.y + bias); // d2,d3
        }
    }
}

// ============================================================
extern "C" void kernel_launch(void* const* d_in, const int* in_sizes, int n_in,
                              void* d_out, int out_size) {
    const float* x      = (const float*)d_in[0];
    const float* w_down = (const float*)d_in[1];
    const float* b_down = (const float*)d_in[2];
    const float* w_enc  = (const float*)d_in[3];
    const float* b_enc  = (const float*)d_in[4];
    const float* w_out  = (const float*)d_in[5];
    const float* b_out  = (const float*)d_in[6];
    float* out = (float*)d_out;

    k_down <<<N_ * H_, 256>>>(x, w_down, b_down);
    k_enc  <<<N_ * H_, 256>>>(w_enc, b_enc);
    k_y    <<<dim3(QL_ / 128, C_ / 64), 256>>>(x, w_out);
    k_fuse <<<N_ * H_, 256>>>(b_out, out);
}

// round 6
// speedup vs baseline: 1.9241x; 1.1116x over previous
#include <cuda_runtime.h>
#include <math.h>

#define N_   4
#define H_   64
#define W_   64
#define C_   256
#define CM_  64
#define E_   100     // enc output channels = 25*4
#define HW_  4096    // H*W
#define QL_  16384   // N * 64 * 64 (low-res pixels)

typedef unsigned long long u64;

// ---- scratch (device globals; allocation-free contract) ----
__device__ float g_down[N_ * CM_ * HW_];        // 4 MB   (N,64,64,64)
__device__ float g_kern[N_ * HW_ * E_];         // 6.5 MB (N,H,W,25,4) flattened
// padded Y: [oc][n][68 rows][72 cols]; interior rows 2..65, cols 4..67.
// Pads are NEVER written -> stay zero from static zero-init (deterministic).
__device__ float g_Yp[C_ * N_ * 68 * 72];       // 20 MB

// ---- f32x2 packed fp32 helpers (FFMA2 path, exact fp32) ----
__device__ __forceinline__ u64 pk2(float a, float b) {
    u64 r;
    asm("mov.b64 %0, {%1, %2};" : "=l"(r)
        : "r"(__float_as_uint(a)), "r"(__float_as_uint(b)));
    return r;
}
__device__ __forceinline__ void fma2(u64& d, u64 a, u64 b) {
    asm("fma.rn.f32x2 %0, %1, %2, %0;" : "+l"(d) : "l"(a), "l"(b));
}
__device__ __forceinline__ float2 up2(u64 v) {
    unsigned int lo, hi;
    asm("mov.b64 {%0, %1}, %2;" : "=r"(lo), "=r"(hi) : "l"(v));
    return make_float2(__uint_as_float(lo), __uint_as_float(hi));
}

// ============================================================
// Kernel 1: 1x1 down conv  (N,256,H,W) -> (N,64,H,W)   [f32x2]
// ============================================================
__global__ __launch_bounds__(256) void k_down(const float* __restrict__ x,
                                              const float* __restrict__ w,
                                              const float* __restrict__ b) {
    __shared__ u64 Ws[64 * 33];                 // [c][k] dup pairs, pitch 33
    __shared__ __align__(16) float Xs[32][64];  // [k][p]
    int n = blockIdx.x >> 6, row = blockIdx.x & 63;
    const float* xb = x + ((size_t)n * C_) * HW_ + row * 64;
    int t = threadIdx.x;
    int pg = t & 15, cg = t >> 4;
    u64 acc[4][2] = {};

    for (int k0 = 0; k0 < 256; k0 += 32) {
        for (int i = t; i < 2048; i += 256) {
            int c = i >> 5, k = i & 31;
            float wv = w[c * 256 + k0 + k];
            Ws[c * 33 + k] = pk2(wv, wv);
        }
        for (int i = t; i < 2048; i += 256) {
            int a = i >> 6, bb = i & 63;
            Xs[a][bb] = xb[(size_t)(k0 + a) * HW_ + bb];
        }
        __syncthreads();
        #pragma unroll 8
        for (int k = 0; k < 32; ++k) {
            float4 xv = *(const float4*)&Xs[k][pg * 4];
            u64 x0 = pk2(xv.x, xv.y), x1 = pk2(xv.z, xv.w);
            #pragma unroll
            for (int cc = 0; cc < 4; ++cc) {
                u64 wv = Ws[(cg * 4 + cc) * 33 + k];
                fma2(acc[cc][0], wv, x0);
                fma2(acc[cc][1], wv, x1);
            }
        }
        __syncthreads();
    }
    #pragma unroll
    for (int cc = 0; cc < 4; ++cc) {
        int c = cg * 4 + cc;
        float bias = b[c];
        float2 lo = up2(acc[cc][0]), hi = up2(acc[cc][1]);
        float4 v = make_float4(lo.x + bias, lo.y + bias, hi.x + bias, hi.y + bias);
        *(float4*)&g_down[((size_t)(n * CM_ + c)) * HW_ + row * 64 + pg * 4] = v;
    }
}

// ============================================================
// Kernel 2: 3x3 enc conv (64->100) + fused softmax over 25  [f32x2 kidx-pairs]
// ============================================================
__global__ __launch_bounds__(256) void k_enc(const float* __restrict__ we,
                                             const float* __restrict__ be) {
    __shared__ __align__(16) u64   Wp[4][12][8][10];  // paired kidx weights
    __shared__ __align__(16) float W24[4][8][12];     // kidx=24 weights
    __shared__ float Xs[8][3][68];                    // [ci][row][w+halo]
    int n = blockIdx.x >> 6, h = blockIdx.x & 63;
    int t = threadIdx.x;
    int p = t & 63, dg = t >> 6;
    u64   accp[12] = {};
    float acc24 = 0.f;

    for (int c0 = 0; c0 < CM_; c0 += 8) {
        for (int i = t; i < 3456; i += 256) {
            int dgi = i / 864, rem = i % 864;
            int kp = rem / 72, rem2 = rem % 72;
            int ci = rem2 / 9, r = rem2 % 9;
            int base = (c0 + ci) * 9 + r;
            float wa = we[(2 * kp * 4 + dgi) * (CM_ * 9) + base];
            float wb = we[((2 * kp + 1) * 4 + dgi) * (CM_ * 9) + base];
            Wp[dgi][kp][ci][r] = pk2(wa, wb);
        }
        for (int i = t; i < 288; i += 256) {
            int dgi = i / 72, rem = i % 72, ci = rem / 9, r = rem % 9;
            W24[dgi][ci][r] = we[(96 + dgi) * (CM_ * 9) + (c0 + ci) * 9 + r];
        }
        for (int i = t; i < 8 * 3 * 66; i += 256) {
            int c = i / 198, rem = i % 198, r = rem / 66, wq = rem % 66;
            int hh = h - 1 + r, ww = wq - 1;
            float v = 0.f;
            if (hh >= 0 && hh < 64 && ww >= 0 && ww < 64)
                v = g_down[((size_t)(n * CM_ + c0 + c) * 64 + hh) * 64 + ww];
            Xs[c][r][wq] = v;
        }
        __syncthreads();

        for (int ci = 0; ci < 8; ++ci) {
            float xr[9];
            u64 xd[9];
            #pragma unroll
            for (int kh = 0; kh < 3; ++kh)
                #pragma unroll
                for (int kw = 0; kw < 3; ++kw)
                    xr[kh * 3 + kw] = Xs[ci][kh][p + kw];
            #pragma unroll
            for (int j = 0; j < 9; ++j) xd[j] = pk2(xr[j], xr[j]);

            #pragma unroll
            for (int kp = 0; kp < 12; ++kp) {
                const u64* wr = &Wp[dg][kp][ci][0];
                ulonglong2 wA = *(const ulonglong2*)wr;
                ulonglong2 wB = *(const ulonglong2*)(wr + 2);
                ulonglong2 wC = *(const ulonglong2*)(wr + 4);
                ulonglong2 wD = *(const ulonglong2*)(wr + 6);
                u64 w8 = wr[8];
                fma2(accp[kp], wA.x, xd[0]); fma2(accp[kp], wA.y, xd[1]);
                fma2(accp[kp], wB.x, xd[2]); fma2(accp[kp], wB.y, xd[3]);
                fma2(accp[kp], wC.x, xd[4]); fma2(accp[kp], wC.y, xd[5]);
                fma2(accp[kp], wD.x, xd[6]); fma2(accp[kp], wD.y, xd[7]);
                fma2(accp[kp], w8, xd[8]);
            }
            const float* w24r = &W24[dg][ci][0];
            float4 wa = *(const float4*)w24r;
            float4 wb = *(const float4*)(w24r + 4);
            float w8s = w24r[8];
            acc24 += wa.x * xr[0] + wa.y * xr[1] + wa.z * xr[2] + wa.w * xr[3]
                   + wb.x * xr[4] + wb.y * xr[5] + wb.z * xr[6] + wb.w * xr[7]
                   + w8s * xr[8];
        }
        __syncthreads();
    }

    float a[25];
    #pragma unroll
    for (int kp = 0; kp < 12; ++kp) {
        float2 f = up2(accp[kp]);
        a[2 * kp] = f.x; a[2 * kp + 1] = f.y;
    }
    a[24] = acc24;
    float m = -1e30f;
    #pragma unroll
    for (int k = 0; k < 25; ++k) { a[k] += be[k * 4 + dg]; m = fmaxf(m, a[k]); }
    float s = 0.f;
    #pragma unroll
    for (int k = 0; k < 25; ++k) { a[k] = expf(a[k] - m); s += a[k]; }
    float inv = 1.f / s;
    float* kp_ = &g_kern[((size_t)(n * HW_ + h * 64 + p)) * E_];
    #pragma unroll
    for (int k = 0; k < 25; ++k) kp_[k * 4 + dg] = a[k] * inv;
}

// ============================================================
// Kernel 3: 1x1 out conv on LOW-RES input -> padded g_Yp (no bias)
// GEMM 256oc x 16384q x 256k; BM=64, BN=128, BK=32
// W in smem as [k][oc] pitch-66 u64 dup-pairs; read as ulonglong2 oc-pairs
// ============================================================
__global__ __launch_bounds__(256) void k_y(const float* __restrict__ x,
                                           const float* __restrict__ w) {
    __shared__ u64 Wd[32 * 66];                      // 16.9 KB
    __shared__ __align__(16) float Xs[32][128];      // 16 KB
    int t = threadIdx.x;
    int qbase = blockIdx.x * 128;
    int ocbase = blockIdx.y * 64;
    int n = qbase >> 12, pos0 = qbase & 4095;        // pos0 % 128 == 0
    const float* xb = x + (size_t)n * (C_ * HW_) + pos0;
    int tq = t & 31, tc = t >> 5;
    int q0 = tq * 4, oc0 = tc * 8;
    u64 acc[8][2] = {};

    for (int k0 = 0; k0 < 256; k0 += 32) {
        for (int i = t; i < 2048; i += 256) {
            int k = i & 31, oc = i >> 5;             // oc const per warp -> coalesced gld
            float wv = w[(ocbase + oc) * 256 + k0 + k];
            Wd[k * 66 + oc] = pk2(wv, wv);
        }
        for (int i = t * 4; i < 4096; i += 1024) {
            int k = i >> 7, q = i & 127;
            *(float4*)&Xs[k][q] = *(const float4*)&xb[(size_t)(k0 + k) * HW_ + q];
        }
        __syncthreads();
        #pragma unroll 8
        for (int k = 0; k < 32; ++k) {
            float4 xv = *(const float4*)&Xs[k][q0];
            u64 xlo = pk2(xv.x, xv.y);
            u64 xhi = pk2(xv.z, xv.w);
            const u64* wrow = &Wd[k * 66 + oc0];     // oc0 even, pitch even -> 16B align
            #pragma unroll
            for (int i = 0; i < 4; ++i) {
                ulonglong2 ww = *(const ulonglong2*)&wrow[2 * i];   // broadcast LDS.128
                fma2(acc[2 * i][0], ww.x, xlo);     fma2(acc[2 * i][1], ww.x, xhi);
                fma2(acc[2 * i + 1][0], ww.y, xlo); fma2(acc[2 * i + 1][1], ww.y, xhi);
            }
        }
        __syncthreads();
    }

    int pos = pos0 + q0;
    int h = pos >> 6, ww_ = pos & 63;                // q0<128, no row wrap in f4
    #pragma unroll
    for (int i = 0; i < 8; ++i) {
        int oc = ocbase + oc0 + i;
        float2 lo = up2(acc[i][0]);
        float2 hi = up2(acc[i][1]);
        float4 v = make_float4(lo.x, lo.y, hi.x, hi.y);
        *(float4*)&g_Yp[(((size_t)oc * N_ + n) * 68 + h + 2) * 72 + 4 + ww_] = v;
    }
}

// ============================================================
// Kernel 4: fused CARAFE reassembly on padded Y + pixel shuffle + bias -> d_out
// block = (n, row), 512 threads; thread = (pixel p, oc-group g of 8), cc=4
// Xs loader = pure contiguous float4 copies (no predicates, no bounds math)
// ============================================================
__global__ __launch_bounds__(512) void k_fuse(const float* __restrict__ bo,
                                              float* __restrict__ out) {
    __shared__ __align__(16) float Ks[64 * 100];   // 25.6 KB
    __shared__ __align__(16) float Xs[32 * 360];   // 46.1 KB (32 ch x 5 rows x 72)
    int n = blockIdx.x >> 6, h = blockIdx.x & 63;
    int t = threadIdx.x;
    int p = t & 63, g = t >> 6;                    // g in 0..7

    {   // g_kern row = 6400 contiguous floats
        const float4* src = (const float4*)&g_kern[((size_t)(n * HW_ + h * 64)) * E_];
        float4* dst = (float4*)Ks;
        for (int i = t; i < 1600; i += 512) dst[i] = src[i];
    }

    for (int c0 = 0; c0 < C_; c0 += 32) {
        __syncthreads();   // prev compute done (also covers Ks fill, iter 0)
        // 32 channels x 90 float4 each, fully contiguous per channel
        for (int i = t; i < 2880; i += 512) {
            int c = i / 90, j = i % 90;
            ((float4*)Xs)[c * 90 + j] = *(const float4*)
                &g_Yp[(((size_t)(c0 + c) * N_ + n) * 68 + h) * 72 + j * 4];
        }
        __syncthreads();

        u64 acc[4][2] = {};
        const float* kr = &Ks[p * 100];
        const float* xbp = &Xs[(g * 4) * 360 + p + 2];   // col of pixel p is 4+p; -2 halo
        #pragma unroll
        for (int kidx = 0; kidx < 25; ++kidx) {
            int ih = kidx / 5, iw = kidx % 5;
            ulonglong2 kk = *(const ulonglong2*)&kr[kidx * 4];  // (d0,d1),(d2,d3)
            int off = ih * 72 + iw;
            #pragma unroll
            for (int cc = 0; cc < 4; ++cc) {
                float xv = xbp[cc * 360 + off];
                u64 xd = pk2(xv, xv);
                fma2(acc[cc][0], kk.x, xd);
                fma2(acc[cc][1], kk.y, xd);
            }
        }
        #pragma unroll
        for (int cc = 0; cc < 4; ++cc) {
            int oc = c0 + g * 4 + cc;
            float bias = bo[oc];
            float2 lo = up2(acc[cc][0]), hi = up2(acc[cc][1]);
            float* op = &out[(((size_t)n * 256 + oc) * 128 + 2 * h) * 128 + 2 * p];
            *(float2*)op         = make_float2(lo.x + bias, lo.y + bias); // d0,d1
            *(float2*)(op + 128) = make_float2(hi.x + bias, hi.y + bias); // d2,d3
        }
    }
}

// ============================================================
extern "C" void kernel_launch(void* const* d_in, const int* in_sizes, int n_in,
                              void* d_out, int out_size) {
    const float* x      = (const float*)d_in[0];
    const float* w_down = (const float*)d_in[1];
    const float* b_down = (const float*)d_in[2];
    const float* w_enc  = (const float*)d_in[3];
    const float* b_enc  = (const float*)d_in[4];
    const float* w_out  = (const float*)d_in[5];
    const float* b_out  = (const float*)d_in[6];
    float* out = (float*)d_out;

    k_down <<<N_ * H_, 256>>>(x, w_down, b_down);
    k_enc  <<<N_ * H_, 256>>>(w_enc, b_enc);
    k_y    <<<dim3(QL_ / 128, C_ / 64), 256>>>(x, w_out);
    k_fuse <<<N_ * H_, 512>>>(b_out, out);
}

// round 15
// speedup vs baseline: 1.9878x; 1.0331x over previous
#include <cuda_runtime.h>
#include <math.h>

#define N_   4
#define H_   64
#define W_   64
#define C_   256
#define CM_  64
#define E_   100     // enc output channels = 25*4
#define HW_  4096    // H*W
#define QL_  16384   // N * 64 * 64 (low-res pixels)

typedef unsigned long long u64;

// ---- scratch (device globals; allocation-free contract) ----
__device__ float g_down[N_ * CM_ * HW_];        // 4 MB   (N,64,64,64)
__device__ float g_kern[N_ * HW_ * E_];         // 6.5 MB (N,H,W,25,4) flattened
// padded Y: [oc][n][68 rows][72 cols]; interior rows 2..65, cols 4..67.
// Pads are NEVER written -> stay zero from static zero-init (deterministic).
__device__ float g_Yp[C_ * N_ * 68 * 72];       // 20 MB

// ---- f32x2 packed fp32 helpers (FFMA2 path, exact fp32) ----
__device__ __forceinline__ u64 pk2(float a, float b) {
    u64 r;
    asm("mov.b64 %0, {%1, %2};" : "=l"(r)
        : "r"(__float_as_uint(a)), "r"(__float_as_uint(b)));
    return r;
}
__device__ __forceinline__ void fma2(u64& d, u64 a, u64 b) {
    asm("fma.rn.f32x2 %0, %1, %2, %0;" : "+l"(d) : "l"(a), "l"(b));
}
__device__ __forceinline__ float2 up2(u64 v) {
    unsigned int lo, hi;
    asm("mov.b64 {%0, %1}, %2;" : "=r"(lo), "=r"(hi) : "l"(v));
    return make_float2(__uint_as_float(lo), __uint_as_float(hi));
}

// ============================================================
// Kernel 1: 1x1 down conv  (N,256,H,W) -> (N,64,H,W)   [f32x2]
// ============================================================
__global__ __launch_bounds__(256) void k_down(const float* __restrict__ x,
                                              const float* __restrict__ w,
                                              const float* __restrict__ b) {
    __shared__ u64 Ws[64 * 33];                 // [c][k] dup pairs, pitch 33
    __shared__ __align__(16) float Xs[32][64];  // [k][p]
    int n = blockIdx.x >> 6, row = blockIdx.x & 63;
    const float* xb = x + ((size_t)n * C_) * HW_ + row * 64;
    int t = threadIdx.x;
    int pg = t & 15, cg = t >> 4;
    u64 acc[4][2] = {};

    for (int k0 = 0; k0 < 256; k0 += 32) {
        for (int i = t; i < 2048; i += 256) {
            int c = i >> 5, k = i & 31;
            float wv = w[c * 256 + k0 + k];
            Ws[c * 33 + k] = pk2(wv, wv);
        }
        for (int i = t; i < 2048; i += 256) {
            int a = i >> 6, bb = i & 63;
            Xs[a][bb] = xb[(size_t)(k0 + a) * HW_ + bb];
        }
        __syncthreads();
        #pragma unroll 8
        for (int k = 0; k < 32; ++k) {
            float4 xv = *(const float4*)&Xs[k][pg * 4];
            u64 x0 = pk2(xv.x, xv.y), x1 = pk2(xv.z, xv.w);
            #pragma unroll
            for (int cc = 0; cc < 4; ++cc) {
                u64 wv = Ws[(cg * 4 + cc) * 33 + k];
                fma2(acc[cc][0], wv, x0);
                fma2(acc[cc][1], wv, x1);
            }
        }
        __syncthreads();
    }
    #pragma unroll
    for (int cc = 0; cc < 4; ++cc) {
        int c = cg * 4 + cc;
        float bias = b[c];
        float2 lo = up2(acc[cc][0]), hi = up2(acc[cc][1]);
        float4 v = make_float4(lo.x + bias, lo.y + bias, hi.x + bias, hi.y + bias);
        *(float4*)&g_down[((size_t)(n * CM_ + c)) * HW_ + row * 64 + pg * 4] = v;
    }
}

// ============================================================
// Kernel 2: 3x3 enc conv (64->100) + fused softmax over 25  [f32x2 kidx-pairs]
// ============================================================
__global__ __launch_bounds__(256) void k_enc(const float* __restrict__ we,
                                             const float* __restrict__ be) {
    __shared__ __align__(16) u64   Wp[4][12][8][10];  // paired kidx weights
    __shared__ __align__(16) float W24[4][8][12];     // kidx=24 weights
    __shared__ float Xs[8][3][68];                    // [ci][row][w+halo]
    int n = blockIdx.x >> 6, h = blockIdx.x & 63;
    int t = threadIdx.x;
    int p = t & 63, dg = t >> 6;
    u64   accp[12] = {};
    float acc24 = 0.f;

    for (int c0 = 0; c0 < CM_; c0 += 8) {
        for (int i = t; i < 3456; i += 256) {
            int dgi = i / 864, rem = i % 864;
            int kp = rem / 72, rem2 = rem % 72;
            int ci = rem2 / 9, r = rem2 % 9;
            int base = (c0 + ci) * 9 + r;
            float wa = we[(2 * kp * 4 + dgi) * (CM_ * 9) + base];
            float wb = we[((2 * kp + 1) * 4 + dgi) * (CM_ * 9) + base];
            Wp[dgi][kp][ci][r] = pk2(wa, wb);
        }
        for (int i = t; i < 288; i += 256) {
            int dgi = i / 72, rem = i % 72, ci = rem / 9, r = rem % 9;
            W24[dgi][ci][r] = we[(96 + dgi) * (CM_ * 9) + (c0 + ci) * 9 + r];
        }
        for (int i = t; i < 8 * 3 * 66; i += 256) {
            int c = i / 198, rem = i % 198, r = rem / 66, wq = rem % 66;
            int hh = h - 1 + r, ww = wq - 1;
            float v = 0.f;
            if (hh >= 0 && hh < 64 && ww >= 0 && ww < 64)
                v = g_down[((size_t)(n * CM_ + c0 + c) * 64 + hh) * 64 + ww];
            Xs[c][r][wq] = v;
        }
        __syncthreads();

        for (int ci = 0; ci < 8; ++ci) {
            float xr[9];
            u64 xd[9];
            #pragma unroll
            for (int kh = 0; kh < 3; ++kh)
                #pragma unroll
                for (int kw = 0; kw < 3; ++kw)
                    xr[kh * 3 + kw] = Xs[ci][kh][p + kw];
            #pragma unroll
            for (int j = 0; j < 9; ++j) xd[j] = pk2(xr[j], xr[j]);

            #pragma unroll
            for (int kp = 0; kp < 12; ++kp) {
                const u64* wr = &Wp[dg][kp][ci][0];
                ulonglong2 wA = *(const ulonglong2*)wr;
                ulonglong2 wB = *(const ulonglong2*)(wr + 2);
                ulonglong2 wC = *(const ulonglong2*)(wr + 4);
                ulonglong2 wD = *(const ulonglong2*)(wr + 6);
                u64 w8 = wr[8];
                fma2(accp[kp], wA.x, xd[0]); fma2(accp[kp], wA.y, xd[1]);
                fma2(accp[kp], wB.x, xd[2]); fma2(accp[kp], wB.y, xd[3]);
                fma2(accp[kp], wC.x, xd[4]); fma2(accp[kp], wC.y, xd[5]);
                fma2(accp[kp], wD.x, xd[6]); fma2(accp[kp], wD.y, xd[7]);
                fma2(accp[kp], w8, xd[8]);
            }
            const float* w24r = &W24[dg][ci][0];
            float4 wa = *(const float4*)w24r;
            float4 wb = *(const float4*)(w24r + 4);
            float w8s = w24r[8];
            acc24 += wa.x * xr[0] + wa.y * xr[1] + wa.z * xr[2] + wa.w * xr[3]
                   + wb.x * xr[4] + wb.y * xr[5] + wb.z * xr[6] + wb.w * xr[7]
                   + w8s * xr[8];
        }
        __syncthreads();
    }

    float a[25];
    #pragma unroll
    for (int kp = 0; kp < 12; ++kp) {
        float2 f = up2(accp[kp]);
        a[2 * kp] = f.x; a[2 * kp + 1] = f.y;
    }
    a[24] = acc24;
    float m = -1e30f;
    #pragma unroll
    for (int k = 0; k < 25; ++k) { a[k] += be[k * 4 + dg]; m = fmaxf(m, a[k]); }
    float s = 0.f;
    #pragma unroll
    for (int k = 0; k < 25; ++k) { a[k] = expf(a[k] - m); s += a[k]; }
    float inv = 1.f / s;
    float* kp_ = &g_kern[((size_t)(n * HW_ + h * 64 + p)) * E_];
    #pragma unroll
    for (int k = 0; k < 25; ++k) kp_[k * 4 + dg] = a[k] * inv;
}

// ============================================================
// Kernel 3: 1x1 out conv on LOW-RES input -> padded g_Yp (no bias)
// GEMM 256oc x 16384q x 256k; BM=64, BN=128, BK=32
// Register-prefetch double buffering hides gmem latency across k-chunks.
// X fill rows: i = t*4 + 1024*j  ->  k = xk0 + 8*j   (1024>>7 == 8)
// ============================================================
__global__ __launch_bounds__(256) void k_y(const float* __restrict__ x,
                                           const float* __restrict__ w) {
    __shared__ u64 Wd[32 * 66];                      // 16.9 KB
    __shared__ __align__(16) float Xs[32][128];      // 16 KB
    int t = threadIdx.x;
    int qbase = blockIdx.x * 128;
    int ocbase = blockIdx.y * 64;
    int n = qbase >> 12, pos0 = qbase & 4095;        // pos0 % 128 == 0
    const float* xb = x + (size_t)n * (C_ * HW_) + pos0;
    int tq = t & 31, tc = t >> 5;
    int q0 = tq * 4, oc0 = tc * 8;
    u64 acc[8][2] = {};

    // fixed per-thread fill coordinates
    int wk = t & 31, woc0 = t >> 5;                  // W: oc = woc0 + 8j
    int xk0 = (t * 4) >> 7, xq = (t * 4) & 127;      // X: k = xk0 + 8j

    float wr[8];
    float4 xr[4];
    #pragma unroll
    for (int j = 0; j < 8; ++j)
        wr[j] = w[(ocbase + woc0 + 8 * j) * 256 + wk];
    #pragma unroll
    for (int j = 0; j < 4; ++j)
        xr[j] = *(const float4*)&xb[(size_t)(xk0 + 8 * j) * HW_ + xq];

    for (int k0 = 0; k0 < 256; k0 += 32) {
        __syncthreads();   // prev compute done
        #pragma unroll
        for (int j = 0; j < 8; ++j)
            Wd[wk * 66 + woc0 + 8 * j] = pk2(wr[j], wr[j]);
        #pragma unroll
        for (int j = 0; j < 4; ++j)
            *(float4*)&Xs[xk0 + 8 * j][xq] = xr[j];
        __syncthreads();

        if (k0 < 224) {   // prefetch next chunk while computing this one
            #pragma unroll
            for (int j = 0; j < 8; ++j)
                wr[j] = w[(ocbase + woc0 + 8 * j) * 256 + k0 + 32 + wk];
            #pragma unroll
            for (int j = 0; j < 4; ++j)
                xr[j] = *(const float4*)&xb[(size_t)(k0 + 32 + xk0 + 8 * j) * HW_ + xq];
        }

        #pragma unroll 8
        for (int k = 0; k < 32; ++k) {
            float4 xv = *(const float4*)&Xs[k][q0];
            u64 xlo = pk2(xv.x, xv.y);
            u64 xhi = pk2(xv.z, xv.w);
            const u64* wrow = &Wd[k * 66 + oc0];     // oc0 even, pitch even -> 16B align
            #pragma unroll
            for (int i = 0; i < 4; ++i) {
                ulonglong2 ww = *(const ulonglong2*)&wrow[2 * i];   // broadcast LDS.128
                fma2(acc[2 * i][0], ww.x, xlo);     fma2(acc[2 * i][1], ww.x, xhi);
                fma2(acc[2 * i + 1][0], ww.y, xlo); fma2(acc[2 * i + 1][1], ww.y, xhi);
            }
        }
    }

    int pos = pos0 + q0;
    int h = pos >> 6, ww_ = pos & 63;                // q0<128, no row wrap in f4
    #pragma unroll
    for (int i = 0; i < 8; ++i) {
        int oc = ocbase + oc0 + i;
        float2 lo = up2(acc[i][0]);
        float2 hi = up2(acc[i][1]);
        float4 v = make_float4(lo.x, lo.y, hi.x, hi.y);
        *(float4*)&g_Yp[(((size_t)oc * N_ + n) * 68 + h + 2) * 72 + 4 + ww_] = v;
    }
}

// ============================================================
// Kernel 4: fused CARAFE reassembly + pixel shuffle + bias -> d_out
// grid = (N*H, 2 channel halves); block = 256 threads = (pixel p, g in 0..3)
// cc=8 channels per thread: amortizes kern LDS (16B kern + 32B x per 16 FFMA2)
// ============================================================
__global__ __launch_bounds__(256) void k_fuse(const float* __restrict__ bo,
                                              float* __restrict__ out) {
    __shared__ __align__(16) float Ks[64 * 100];   // 25.6 KB
    __shared__ __align__(16) float Xs[32 * 360];   // 46.1 KB (32 ch x 5 rows x 72)
    int n = blockIdx.x >> 6, h = blockIdx.x & 63;
    int cbase = blockIdx.y << 7;                   // 0 or 128
    int t = threadIdx.x;
    int p = t & 63, g = t >> 6;                    // g in 0..3

    {   // g_kern row = 6400 contiguous floats
        const float4* src = (const float4*)&g_kern[((size_t)(n * HW_ + h * 64)) * E_];
        float4* dst = (float4*)Ks;
        for (int i = t; i < 1600; i += 256) dst[i] = src[i];
    }

    for (int c0 = cbase; c0 < cbase + 128; c0 += 32) {
        __syncthreads();   // prev compute done (also covers Ks fill, iter 0)
        // 32 channels x 90 float4 each, fully contiguous per channel
        for (int i = t; i < 2880; i += 256) {
            int c = i / 90, j = i % 90;
            ((float4*)Xs)[i] = *(const float4*)
                &g_Yp[(((size_t)(c0 + c) * N_ + n) * 68 + h) * 72 + j * 4];
        }
        __syncthreads();

        u64 acc[8][2] = {};
        const float* kr = &Ks[p * 100];
        const float* xbp = &Xs[(g * 8) * 360 + p + 2];   // col of pixel p is 4+p; -2 halo
        #pragma unroll
        for (int kidx = 0; kidx < 25; ++kidx) {
            int ih = kidx / 5, iw = kidx % 5;
            ulonglong2 kk = *(const ulonglong2*)&kr[kidx * 4];  // (d0,d1),(d2,d3)
            int off = ih * 72 + iw;
            #pragma unroll
            for (int cc = 0; cc < 8; ++cc) {
                float xv = xbp[cc * 360 + off];
                u64 xd = pk2(xv, xv);
                fma2(acc[cc][0], kk.x, xd);
                fma2(acc[cc][1], kk.y, xd);
            }
        }
        #pragma unroll
        for (int cc = 0; cc < 8; ++cc) {
            int oc = c0 + g * 8 + cc;
            float bias = bo[oc];
            float2 lo = up2(acc[cc][0]), hi = up2(acc[cc][1]);
            float* op = &out[(((size_t)n * 256 + oc) * 128 + 2 * h) * 128 + 2 * p];
            *(float2*)op         = make_float2(lo.x + bias, lo.y + bias); // d0,d1
            *(float2*)(op + 128) = make_float2(hi.x + bias, hi.y + bias); // d2,d3
        }
    }
}

// ============================================================
extern "C" void kernel_launch(void* const* d_in, const int* in_sizes, int n_in,
                              void* d_out, int out_size) {
    const float* x      = (const float*)d_in[0];
    const float* w_down = (const float*)d_in[1];
    const float* b_down = (const float*)d_in[2];
    const float* w_enc  = (const float*)d_in[3];
    const float* b_enc  = (const float*)d_in[4];
    const float* w_out  = (const float*)d_in[5];
    const float* b_out  = (const float*)d_in[6];
    float* out = (float*)d_out;

    k_down <<<N_ * H_, 256>>>(x, w_down, b_down);
    k_enc  <<<N_ * H_, 256>>>(w_enc, b_enc);
    k_y    <<<dim3(QL_ / 128, C_ / 64), 256>>>(x, w_out);
    k_fuse <<<dim3(N_ * H_, 2), 256>>>(b_out, out);
}

// round 16
// speedup vs baseline: 2.0715x; 1.0421x over previous
#include <cuda_runtime.h>
#include <math.h>

#define N_   4
#define H_   64
#define W_   64
#define C_   256
#define CM_  64
#define E_   100     // enc output channels = 25*4
#define HW_  4096    // H*W
#define QL_  16384   // N * 64 * 64 (low-res pixels)

typedef unsigned long long u64;

// ---- scratch (device globals; allocation-free contract) ----
__device__ float g_down[N_ * CM_ * HW_];        // 4 MB   (N,64,64,64)
__device__ float g_kern[N_ * HW_ * E_];         // 6.5 MB (N,H,W,25,4) flattened
// padded Y: [oc][n][68 rows][72 cols]; interior rows 2..65, cols 4..67.
// Pads are NEVER written -> stay zero from static zero-init (deterministic).
__device__ float g_Yp[C_ * N_ * 68 * 72];       // 20 MB

// ---- f32x2 packed fp32 helpers (FFMA2 path, exact fp32) ----
__device__ __forceinline__ u64 pk2(float a, float b) {
    u64 r;
    asm("mov.b64 %0, {%1, %2};" : "=l"(r)
        : "r"(__float_as_uint(a)), "r"(__float_as_uint(b)));
    return r;
}
__device__ __forceinline__ void fma2(u64& d, u64 a, u64 b) {
    asm("fma.rn.f32x2 %0, %1, %2, %0;" : "+l"(d) : "l"(a), "l"(b));
}
__device__ __forceinline__ float2 up2(u64 v) {
    unsigned int lo, hi;
    asm("mov.b64 {%0, %1}, %2;" : "=r"(lo), "=r"(hi) : "l"(v));
    return make_float2(__uint_as_float(lo), __uint_as_float(hi));
}

// ============================================================
// Kernel 1: 1x1 down conv  (N,256,H,W) -> (N,64,H,W)   [f32x2]
// ============================================================
__global__ __launch_bounds__(256) void k_down(const float* __restrict__ x,
                                              const float* __restrict__ w,
                                              const float* __restrict__ b) {
    __shared__ u64 Ws[64 * 33];                 // [c][k] dup pairs, pitch 33
    __shared__ __align__(16) float Xs[32][64];  // [k][p]
    int n = blockIdx.x >> 6, row = blockIdx.x & 63;
    const float* xb = x + ((size_t)n * C_) * HW_ + row * 64;
    int t = threadIdx.x;
    int pg = t & 15, cg = t >> 4;
    u64 acc[4][2] = {};

    for (int k0 = 0; k0 < 256; k0 += 32) {
        for (int i = t; i < 2048; i += 256) {
            int c = i >> 5, k = i & 31;
            float wv = w[c * 256 + k0 + k];
            Ws[c * 33 + k] = pk2(wv, wv);
        }
        for (int i = t; i < 2048; i += 256) {
            int a = i >> 6, bb = i & 63;
            Xs[a][bb] = xb[(size_t)(k0 + a) * HW_ + bb];
        }
        __syncthreads();
        #pragma unroll 8
        for (int k = 0; k < 32; ++k) {
            float4 xv = *(const float4*)&Xs[k][pg * 4];
            u64 x0 = pk2(xv.x, xv.y), x1 = pk2(xv.z, xv.w);
            #pragma unroll
            for (int cc = 0; cc < 4; ++cc) {
                u64 wv = Ws[(cg * 4 + cc) * 33 + k];
                fma2(acc[cc][0], wv, x0);
                fma2(acc[cc][1], wv, x1);
            }
        }
        __syncthreads();
    }
    #pragma unroll
    for (int cc = 0; cc < 4; ++cc) {
        int c = cg * 4 + cc;
        float bias = b[c];
        float2 lo = up2(acc[cc][0]), hi = up2(acc[cc][1]);
        float4 v = make_float4(lo.x + bias, lo.y + bias, hi.x + bias, hi.y + bias);
        *(float4*)&g_down[((size_t)(n * CM_ + c)) * HW_ + row * 64 + pg * 4] = v;
    }
}

// ============================================================
// k_mid: block-specialized merge of k_enc (blocks 0..255) and k_y
// (blocks 256..767). The two are data-independent; co-scheduling
// overlaps them instead of serializing two launches.
// ============================================================
#define SMEM_BYTES 38784   // max(enc: 30720+1536+6528, y: 16896+16384)

// ---- enc body: 3x3 conv (64->100) + fused softmax over 25 ----
__device__ __forceinline__ void enc_body(char* sm, int bid,
                                         const float* __restrict__ we,
                                         const float* __restrict__ be) {
    u64   (*Wp)[12][8][10] = (u64(*)[12][8][10])sm;          // 30720 B
    float (*W24)[8][12]    = (float(*)[8][12])(sm + 30720);  // 1536 B
    float (*Xs)[3][68]     = (float(*)[3][68])(sm + 32256);  // 6528 B
    int n = bid >> 6, h = bid & 63;
    int t = threadIdx.x;
    int p = t & 63, dg = t >> 6;
    u64   accp[12] = {};
    float acc24 = 0.f;

    for (int c0 = 0; c0 < CM_; c0 += 8) {
        for (int i = t; i < 3456; i += 256) {
            int dgi = i / 864, rem = i % 864;
            int kp = rem / 72, rem2 = rem % 72;
            int ci = rem2 / 9, r = rem2 % 9;
            int base = (c0 + ci) * 9 + r;
            float wa = we[(2 * kp * 4 + dgi) * (CM_ * 9) + base];
            float wb = we[((2 * kp + 1) * 4 + dgi) * (CM_ * 9) + base];
            Wp[dgi][kp][ci][r] = pk2(wa, wb);
        }
        for (int i = t; i < 288; i += 256) {
            int dgi = i / 72, rem = i % 72, ci = rem / 9, r = rem % 9;
            W24[dgi][ci][r] = we[(96 + dgi) * (CM_ * 9) + (c0 + ci) * 9 + r];
        }
        for (int i = t; i < 8 * 3 * 66; i += 256) {
            int c = i / 198, rem = i % 198, r = rem / 66, wq = rem % 66;
            int hh = h - 1 + r, ww = wq - 1;
            float v = 0.f;
            if (hh >= 0 && hh < 64 && ww >= 0 && ww < 64)
                v = g_down[((size_t)(n * CM_ + c0 + c) * 64 + hh) * 64 + ww];
            Xs[c][r][wq] = v;
        }
        __syncthreads();

        for (int ci = 0; ci < 8; ++ci) {
            float xr[9];
            u64 xd[9];
            #pragma unroll
            for (int kh = 0; kh < 3; ++kh)
                #pragma unroll
                for (int kw = 0; kw < 3; ++kw)
                    xr[kh * 3 + kw] = Xs[ci][kh][p + kw];
            #pragma unroll
            for (int j = 0; j < 9; ++j) xd[j] = pk2(xr[j], xr[j]);

            #pragma unroll
            for (int kp = 0; kp < 12; ++kp) {
                const u64* wr = &Wp[dg][kp][ci][0];
                ulonglong2 wA = *(const ulonglong2*)wr;
                ulonglong2 wB = *(const ulonglong2*)(wr + 2);
                ulonglong2 wC = *(const ulonglong2*)(wr + 4);
                ulonglong2 wD = *(const ulonglong2*)(wr + 6);
                u64 w8 = wr[8];
                fma2(accp[kp], wA.x, xd[0]); fma2(accp[kp], wA.y, xd[1]);
                fma2(accp[kp], wB.x, xd[2]); fma2(accp[kp], wB.y, xd[3]);
                fma2(accp[kp], wC.x, xd[4]); fma2(accp[kp], wC.y, xd[5]);
                fma2(accp[kp], wD.x, xd[6]); fma2(accp[kp], wD.y, xd[7]);
                fma2(accp[kp], w8, xd[8]);
            }
            const float* w24r = &W24[dg][ci][0];
            float4 wa = *(const float4*)w24r;
            float4 wb = *(const float4*)(w24r + 4);
            float w8s = w24r[8];
            acc24 += wa.x * xr[0] + wa.y * xr[1] + wa.z * xr[2] + wa.w * xr[3]
                   + wb.x * xr[4] + wb.y * xr[5] + wb.z * xr[6] + wb.w * xr[7]
                   + w8s * xr[8];
        }
        __syncthreads();
    }

    float a[25];
    #pragma unroll
    for (int kp = 0; kp < 12; ++kp) {
        float2 f = up2(accp[kp]);
        a[2 * kp] = f.x; a[2 * kp + 1] = f.y;
    }
    a[24] = acc24;
    float m = -1e30f;
    #pragma unroll
    for (int k = 0; k < 25; ++k) { a[k] += be[k * 4 + dg]; m = fmaxf(m, a[k]); }
    float s = 0.f;
    #pragma unroll
    for (int k = 0; k < 25; ++k) { a[k] = expf(a[k] - m); s += a[k]; }
    float inv = 1.f / s;
    float* kp_ = &g_kern[((size_t)(n * HW_ + h * 64 + p)) * E_];
    #pragma unroll
    for (int k = 0; k < 25; ++k) kp_[k * 4 + dg] = a[k] * inv;
}

// ---- y body: 1x1 out conv (no bias) -> padded g_Yp, reg-prefetched ----
__device__ __forceinline__ void y_body(char* sm, int yid,
                                       const float* __restrict__ x,
                                       const float* __restrict__ w) {
    u64* Wd = (u64*)sm;                                   // 32*66*8 = 16896 B
    float (*Xs)[128] = (float(*)[128])(sm + 16896);       // 16384 B
    int t = threadIdx.x;
    int qbase = (yid & 127) * 128;
    int ocbase = (yid >> 7) * 64;
    int n = qbase >> 12, pos0 = qbase & 4095;             // pos0 % 128 == 0
    const float* xb = x + (size_t)n * (C_ * HW_) + pos0;
    int tq = t & 31, tc = t >> 5;
    int q0 = tq * 4, oc0 = tc * 8;
    u64 acc[8][2] = {};

    int wk = t & 31, woc0 = t >> 5;                       // W: oc = woc0 + 8j
    int xk0 = (t * 4) >> 7, xq = (t * 4) & 127;           // X: k = xk0 + 8j

    float wr[8];
    float4 xr[4];
    #pragma unroll
    for (int j = 0; j < 8; ++j)
        wr[j] = w[(ocbase + woc0 + 8 * j) * 256 + wk];
    #pragma unroll
    for (int j = 0; j < 4; ++j)
        xr[j] = *(const float4*)&xb[(size_t)(xk0 + 8 * j) * HW_ + xq];

    for (int k0 = 0; k0 < 256; k0 += 32) {
        __syncthreads();   // prev compute done
        #pragma unroll
        for (int j = 0; j < 8; ++j)
            Wd[wk * 66 + woc0 + 8 * j] = pk2(wr[j], wr[j]);
        #pragma unroll
        for (int j = 0; j < 4; ++j)
            *(float4*)&Xs[xk0 + 8 * j][xq] = xr[j];
        __syncthreads();

        if (k0 < 224) {   // prefetch next chunk while computing this one
            #pragma unroll
            for (int j = 0; j < 8; ++j)
                wr[j] = w[(ocbase + woc0 + 8 * j) * 256 + k0 + 32 + wk];
            #pragma unroll
            for (int j = 0; j < 4; ++j)
                xr[j] = *(const float4*)&xb[(size_t)(k0 + 32 + xk0 + 8 * j) * HW_ + xq];
        }

        #pragma unroll 8
        for (int k = 0; k < 32; ++k) {
            float4 xv = *(const float4*)&Xs[k][q0];
            u64 xlo = pk2(xv.x, xv.y);
            u64 xhi = pk2(xv.z, xv.w);
            const u64* wrow = &Wd[k * 66 + oc0];   // oc0 even, pitch even -> 16B align
            #pragma unroll
            for (int i = 0; i < 4; ++i) {
                ulonglong2 ww = *(const ulonglong2*)&wrow[2 * i];   // broadcast LDS.128
                fma2(acc[2 * i][0], ww.x, xlo);     fma2(acc[2 * i][1], ww.x, xhi);
                fma2(acc[2 * i + 1][0], ww.y, xlo); fma2(acc[2 * i + 1][1], ww.y, xhi);
            }
        }
    }

    int pos = pos0 + q0;
    int h = pos >> 6, ww_ = pos & 63;
    #pragma unroll
    for (int i = 0; i < 8; ++i) {
        int oc = ocbase + oc0 + i;
        float2 lo = up2(acc[i][0]);
        float2 hi = up2(acc[i][1]);
        float4 v = make_float4(lo.x, lo.y, hi.x, hi.y);
        *(float4*)&g_Yp[(((size_t)oc * N_ + n) * 68 + h + 2) * 72 + 4 + ww_] = v;
    }
}

__global__ __launch_bounds__(256) void k_mid(const float* __restrict__ x,
                                             const float* __restrict__ we,
                                             const float* __restrict__ be,
                                             const float* __restrict__ wo) {
    __shared__ __align__(16) char sm[SMEM_BYTES];
    int bid = blockIdx.x;
    if (bid < 256) enc_body(sm, bid, we, be);       // longer blocks first (LPT)
    else           y_body(sm, bid - 256, x, wo);
}

// ============================================================
// Kernel 3: fused CARAFE reassembly + pixel shuffle + bias -> d_out
// grid = (N*H, 2 channel halves); block = 256 threads = (pixel p, g in 0..3)
// ============================================================
__global__ __launch_bounds__(256) void k_fuse(const float* __restrict__ bo,
                                              float* __restrict__ out) {
    __shared__ __align__(16) float Ks[64 * 100];   // 25.6 KB
    __shared__ __align__(16) float Xs[32 * 360];   // 46.1 KB (32 ch x 5 rows x 72)
    int n = blockIdx.x >> 6, h = blockIdx.x & 63;
    int cbase = blockIdx.y << 7;                   // 0 or 128
    int t = threadIdx.x;
    int p = t & 63, g = t >> 6;                    // g in 0..3

    {   // g_kern row = 6400 contiguous floats
        const float4* src = (const float4*)&g_kern[((size_t)(n * HW_ + h * 64)) * E_];
        float4* dst = (float4*)Ks;
        for (int i = t; i < 1600; i += 256) dst[i] = src[i];
    }

    for (int c0 = cbase; c0 < cbase + 128; c0 += 32) {
        __syncthreads();   // prev compute done (also covers Ks fill, iter 0)
        for (int i = t; i < 2880; i += 256) {
            int c = i / 90, j = i % 90;
            ((float4*)Xs)[i] = *(const float4*)
                &g_Yp[(((size_t)(c0 + c) * N_ + n) * 68 + h) * 72 + j * 4];
        }
        __syncthreads();

        u64 acc[8][2] = {};
        const float* kr = &Ks[p * 100];
        const float* xbp = &Xs[(g * 8) * 360 + p + 2];
        #pragma unroll
        for (int kidx = 0; kidx < 25; ++kidx) {
            int ih = kidx / 5, iw = kidx % 5;
            ulonglong2 kk = *(const ulonglong2*)&kr[kidx * 4];  // (d0,d1),(d2,d3)
            int off = ih * 72 + iw;
            #pragma unroll
            for (int cc = 0; cc < 8; ++cc) {
                float xv = xbp[cc * 360 + off];
                u64 xd = pk2(xv, xv);
                fma2(acc[cc][0], kk.x, xd);
                fma2(acc[cc][1], kk.y, xd);
            }
        }
        #pragma unroll
        for (int cc = 0; cc < 8; ++cc) {
            int oc = c0 + g * 8 + cc;
            float bias = bo[oc];
            float2 lo = up2(acc[cc][0]), hi = up2(acc[cc][1]);
            float* op = &out[(((size_t)n * 256 + oc) * 128 + 2 * h) * 128 + 2 * p];
            *(float2*)op         = make_float2(lo.x + bias, lo.y + bias); // d0,d1
            *(float2*)(op + 128) = make_float2(hi.x + bias, hi.y + bias); // d2,d3
        }
    }
}

// ============================================================
extern "C" void kernel_launch(void* const* d_in, const int* in_sizes, int n_in,
                              void* d_out, int out_size) {
    const float* x      = (const float*)d_in[0];
    const float* w_down = (const float*)d_in[1];
    const float* b_down = (const float*)d_in[2];
    const float* w_enc  = (const float*)d_in[3];
    const float* b_enc  = (const float*)d_in[4];
    const float* w_out  = (const float*)d_in[5];
    const float* b_out  = (const float*)d_in[6];
    float* out = (float*)d_out;

    k_down <<<N_ * H_, 256>>>(x, w_down, b_down);
    k_mid  <<<768, 256>>>(x, w_enc, b_enc, w_out);   // enc (256) + y (512) co-scheduled
    k_fuse <<<dim3(N_ * H_, 2), 256>>>(b_out, out);
}